// round 11
// baseline (speedup 1.0000x reference)
#include <cuda_runtime.h>
#include <math.h>
#include <stdint.h>

#define BB  32
#define MM  65536
#define WD  32
#define RR  4
#define KK  16
#define CC  65
#define INS 256
#define NEG_INF (-3.402823e38f)
#define POS_INF ( 3.402823e38f)
#define FULLMASK 0xffffffffu

// ---------------- scratch ----------------
__device__ __align__(16) float g_rq[BB * RR * WD];
__device__ __align__(16) float g_proj[BB * 98];          // pre-sigmoid rows 128..225
__device__ __align__(16) float g_newvis[BB * CC * WD];
__device__ float g_newusage[BB * CC];
__device__ int   g_topk[BB * RR * KK];
// candidates: per (b,r): 32 chunks * 16 = 512 (each chunk-list sorted desc)
__device__ __align__(16) unsigned g_cand_v[BB * RR * 512];
__device__ __align__(16) int      g_cand_i[BB * RR * 512];
// segmented argmin partials: per b: 32 chunks
__device__ float g_seg_minv[BB * 32];
__device__ int   g_seg_mini[BB * 32];

// order-preserving float <-> u32 maps
__device__ __forceinline__ unsigned fmap(float x) {
    unsigned u = __float_as_uint(x);
    return (u & 0x80000000u) ? ~u : (u | 0x80000000u);
}
__device__ __forceinline__ float funmap(unsigned u) {
    unsigned v = (u & 0x80000000u) ? (u & 0x7fffffffu) : ~u;
    return __uint_as_float(v);
}

__device__ __forceinline__ void cp_async16(void* smem_dst, const void* gsrc) {
    unsigned sa = (unsigned)__cvta_generic_to_shared(smem_dst);
    asm volatile("cp.async.cg.shared.global [%0], [%1], 16;\n" :: "r"(sa), "l"(gsrc));
}
#define CP_COMMIT() asm volatile("cp.async.commit_group;\n" ::: "memory")
#define CP_WAIT2()  asm volatile("cp.async.wait_group 2;\n" ::: "memory")
#define CP_WAIT1()  asm volatile("cp.async.wait_group 1;\n" ::: "memory")
#define CP_WAIT0()  asm volatile("cp.async.wait_group 0;\n" ::: "memory")

// ---------------- kernel 1a: projections (grid 32 x 4) ----------------
__global__ void k_proj(const float* __restrict__ xi,
                       const float* __restrict__ Wrq, const float* __restrict__ brq,
                       const float* __restrict__ Wwv, const float* __restrict__ bwv,
                       const float* __restrict__ Wig, const float* __restrict__ big,
                       const float* __restrict__ Wwg, const float* __restrict__ bwg)
{
    int b  = blockIdx.x;
    int gy = blockIdx.y;          // 4 groups of 64 rows
    int t = threadIdx.x;          // 128
    int w = t >> 5, l = t & 31;
    int sub = l & 7;

    __shared__ float4 s_xi4[INS / 4];
    if (t < 64) s_xi4[t] = ((const float4*)(xi + b * INS))[t];
    __syncthreads();

#pragma unroll 1
    for (int pass = 0; pass < 4; pass++) {
        int row = gy * 64 + pass * 16 + w * 4 + (l >> 3);
        float acc = 0.f;
        if (row < 226) {
            const float4* wp;
            if (row < 128)      wp = (const float4*)(Wrq + row * INS);
            else if (row < 160) wp = (const float4*)(Wwv + (row - 128) * INS);
            else if (row < 225) wp = (const float4*)(Wig + (row - 160) * INS);
            else                wp = (const float4*)Wwg;
#pragma unroll
            for (int m = 0; m < 8; m++) {
                float4 a = wp[sub + m * 8];
                float4 q = s_xi4[sub + m * 8];
                acc += a.x * q.x + a.y * q.y + a.z * q.z + a.w * q.w;
            }
        }
        acc += __shfl_xor_sync(FULLMASK, acc, 1);
        acc += __shfl_xor_sync(FULLMASK, acc, 2);
        acc += __shfl_xor_sync(FULLMASK, acc, 4);
        if (sub == 0 && row < 226) {
            if (row < 128)      g_rq[b * 128 + row] = acc + brq[row];
            else if (row < 160) g_proj[b * 98 + (row - 128)] = acc + bwv[row - 128];
            else if (row < 225) g_proj[b * 98 + 32 + (row - 160)] = acc + big[row - 160];
            else                g_proj[b * 98 + 97] = acc + bwg[0];
        }
    }
}

// ---------------- kernel 1b: write-phase ----------------
__global__ void k_write(const float* __restrict__ rw,
                        const float* __restrict__ ww,
                        const float* __restrict__ usage,
                        const float* __restrict__ vis,
                        const int* __restrict__ rpos,
                        const int* __restrict__ tptr)
{
    int b = blockIdx.x;
    int t = threadIdx.x;   // 128

    __shared__ float s_wv[WD];
    __shared__ float s_ig[CC];
    __shared__ float s_wg;
    __shared__ float s_ru[CC], s_rwg[CC], s_wwg[CC], s_I[CC], s_wwn[CC];
    __shared__ float s_minu;
    __shared__ int   s_p[CC];

    if (t < 32) s_wv[t] = g_proj[b * 98 + t];
    if (t < CC) s_ig[t] = 1.0f / (1.0f + expf(-g_proj[b * 98 + 32 + t]));
    if (t == 127) s_wg = 1.0f / (1.0f + expf(-g_proj[b * 98 + 97]));

    int ts = tptr ? *tptr : 2;

    if (t < CC) {
        int p = rpos[b * CC + t];
        s_p[t] = p;
        float rg = rw[(size_t)b * MM + p];
        if (ts == 1) rg += 1.0f;
        s_rwg[t] = rg;
        s_wwg[t] = ww[(size_t)b * MM + p];
        s_ru[t]  = usage[(size_t)b * MM + p];
    }
    __syncthreads();
    if (t == 0) {
        float mn = s_ru[0];
        for (int c = 1; c < CC; c++) mn = fminf(mn, s_ru[c]);
        s_minu = mn;
    }
    __syncthreads();
    if (t < CC) {
        float I = (s_ru[t] == s_minu) ? 1.0f : 0.0f;
        s_I[t] = I;
        float u = ((s_rwg[t] + s_wwg[t]) > 0.005f) ? 1.0f : 0.0f;
        float nru = (u > 0.0f) ? ((float)ts - s_ru[t]) : s_ru[t];
        g_newusage[b * CC + t] = nru;
        s_wwn[t] = s_wg * (s_ig[t] * s_rwg[t] + (1.0f - s_ig[t]) * I);
    }
    __syncthreads();
    for (int idx = t; idx < CC * WD; idx += blockDim.x) {
        int c = idx >> 5, ww2 = idx & 31;
        float nv = vis[(size_t)b * CC * WD + idx] * (1.0f - s_I[c]) + s_wwn[c] * s_wv[ww2];
        g_newvis[(size_t)b * CC * WD + idx] = nv;
    }
}

// ---------------- kernel 2: 3-stage cp.async scores + warp-parallel top-16 + fused argmin ----------------
__global__ void __launch_bounds__(128, 4) k_scores(const float* __restrict__ memory,
                                                   const float* __restrict__ usage,
                                                   const int* __restrict__ rpos)
{
    extern __shared__ float4 s_t[];      // 3 tiles x 1024 float4 = 48 KB; reused for scores

    int b = blockIdx.y;
    int chunk = blockIdx.x;      // 32 chunks of 2048 rows
    int t = threadIdx.x;         // 128
    int w = t >> 5, l = t & 31;
    int chunkbase = chunk * 2048;

    __shared__ float4 s_q4[RR * 8];
    __shared__ int   s_p[CC];
    __shared__ int   s_last[CC];
    __shared__ unsigned s_bm[64];        // 2048-bit bitmap of scattered rows in this chunk
    __shared__ unsigned s_wm[4], s_wk[4];

    if (t < 64)     s_bm[t] = 0u;
    if (t < RR * 8) s_q4[t] = ((const float4*)g_rq)[b * RR * 8 + t];
    if (t < CC)     s_p[t] = rpos[b * CC + t];
    __syncthreads();
    if (t < CC) {
        int lastf = 1;
        for (int c2 = t + 1; c2 < CC; c2++) if (s_p[c2] == s_p[t]) { lastf = 0; break; }
        s_last[t] = lastf;
        int p = s_p[t];
        if (p >= chunkbase && p < chunkbase + 2048) {
            int loc = p - chunkbase;
            atomicOr(&s_bm[loc >> 5], 1u << (loc & 31));
        }
    }

    unsigned u0[16], u1[16], u2[16], u3[16];

    const float* gbase = memory + ((size_t)b * MM + chunkbase) * WD;
    const float4* src = (const float4*)gbase;

    // prologue: issue tiles 0 and 1
#pragma unroll
    for (int pr = 0; pr < 2; pr++) {
#pragma unroll
        for (int j = 0; j < 8; j++) {
            int f = j * 128 + t;
            int row = f >> 3, col = f & 7;
            cp_async16(&s_t[pr * 1024 + row * 8 + (col ^ (row & 7))], src + pr * 1024 + f);
        }
        CP_COMMIT();
    }

#pragma unroll
    for (int tile = 0; tile < 16; tile++) {
        int bufbase = (tile % 3) * 1024;
        __syncthreads();   // prior readers of buffer (tile+2)%3 are done
        if (tile < 14) {
            int nb = ((tile + 2) % 3) * 1024;
            const float4* s2 = src + (size_t)(tile + 2) * 1024;
#pragma unroll
            for (int j = 0; j < 8; j++) {
                int f = j * 128 + t;
                int row = f >> 3, col = f & 7;
                cp_async16(&s_t[nb + row * 8 + (col ^ (row & 7))], s2 + f);
            }
            CP_COMMIT();
            CP_WAIT2();
        } else if (tile == 14) { CP_WAIT1(); }
        else                   { CP_WAIT0(); }
        __syncthreads();   // current tile visible block-wide
        int base = chunkbase + tile * 128;
        if (t < CC && s_last[t]) {
            int p = s_p[t];
            if (p >= base && p < base + 128) {
                int loc = p - base;
                const float4* nv = (const float4*)(g_newvis + ((size_t)b * CC + t) * WD);
#pragma unroll
                for (int j = 0; j < 8; j++) s_t[bufbase + loc * 8 + (j ^ (loc & 7))] = nv[j];
            }
        }
        __syncthreads();
        float a0 = 0.f, a1 = 0.f, a2 = 0.f, a3 = 0.f;
#pragma unroll
        for (int j = 0; j < 8; j++) {
            float4 x = s_t[bufbase + t * 8 + (j ^ (t & 7))];
            float4 q0 = s_q4[j], q1 = s_q4[8 + j], q2 = s_q4[16 + j], q3 = s_q4[24 + j];
            a0 += x.x * q0.x + x.y * q0.y + x.z * q0.z + x.w * q0.w;
            a1 += x.x * q1.x + x.y * q1.y + x.z * q1.z + x.w * q1.w;
            a2 += x.x * q2.x + x.y * q2.y + x.z * q2.z + x.w * q2.w;
            a3 += x.x * q3.x + x.y * q3.y + x.z * q3.z + x.w * q3.w;
        }
        u0[tile] = fmap(a0); u1[tile] = fmap(a1);
        u2[tile] = fmap(a2); u3[tile] = fmap(a3);
    }

    // ---- transpose scores into smem (tile buffers are free now) ----
    __syncthreads();   // all tile reads done before overwrite
    unsigned* s_sc = (unsigned*)s_t;   // 4 * 2048 u32 = 32 KB (of 48 KB)
#pragma unroll
    for (int tile = 0; tile < 16; tile++) {
        int rowi = tile * 128 + t;
        s_sc[0 * 2048 + rowi] = u0[tile];
        s_sc[1 * 2048 + rowi] = u1[tile];
        s_sc[2 * 2048 + rowi] = u2[tile];
        s_sc[3 * 2048 + rowi] = u3[tile];
    }
    __syncthreads();

    // ---- warp w selects top-16 of 2048 scores for query r = w ----
    {
        const unsigned* sc = s_sc + w * 2048;
        unsigned m1 = 0u, m2 = 0u;
        int i1 = l, i2 = l;
        for (int j = 0; j < 64; j++) {
            unsigned v = sc[j * 32 + l];
            int idx = j * 32 + l;
            if (v > m1)      { m2 = m1; i2 = i1; m1 = v; i1 = idx; }
            else if (v > m2) { m2 = v; i2 = idx; }
        }
        unsigned rem_lo = 0u, rem_hi = 0u;
        bool have2 = true;
        unsigned lm = m1; int li = i1;

        unsigned* outv = g_cand_v + ((size_t)(b * RR) * 32 + chunk) * 16 + (size_t)w * 32 * 16;
        int*      outi = g_cand_i + ((size_t)(b * RR) * 32 + chunk) * 16 + (size_t)w * 32 * 16;

        for (int round = 0; round < 16; round++) {
            unsigned m = __reduce_max_sync(FULLMASK, lm);
            unsigned key = (lm == m) ? (unsigned)li : 0xffffffffu;
            unsigned k = __reduce_min_sync(FULLMASK, key);
            if (l == 0) { outv[round] = m; outi[round] = chunkbase + (int)k; }
            if (lm == m && (unsigned)li == k) {
                int j = li >> 5;
                if (j < 32) rem_lo |= 1u << j; else rem_hi |= 1u << (j - 32);
                if (have2) { lm = m2; li = i2; have2 = false; }
                else {
                    lm = 0u; li = l;
                    for (int jj = 0; jj < 64; jj++) {
                        bool rm = (jj < 32) ? ((rem_lo >> jj) & 1u) : ((rem_hi >> (jj - 32)) & 1u);
                        unsigned v = rm ? 0u : sc[jj * 32 + l];
                        if (v > lm) { lm = v; li = jj * 32 + l; }
                    }
                }
            }
        }
    }

    // ---- fused usage argmin over this chunk (excluding scattered rows) ----
    {
        const float4* u4 = (const float4*)(usage + (size_t)b * MM + chunkbase);
        unsigned bu = 0xffffffffu;
        int      bi = 0x7fffffff;
#pragma unroll
        for (int i = 0; i < 4; i++) {
            float4 x = u4[i * 128 + t];
            int lbase = (i * 128 + t) << 2;
            float xs[4] = {x.x, x.y, x.z, x.w};
#pragma unroll
            for (int j = 0; j < 4; j++) {
                int loc = lbase + j;
                unsigned uv = ((s_bm[loc >> 5] >> (loc & 31)) & 1u) ? 0xffffffffu : fmap(xs[j]);
                int gi = chunkbase + loc;
                if (uv < bu || (uv == bu && gi < bi)) { bu = uv; bi = gi; }
            }
        }
        unsigned m_w = __reduce_min_sync(FULLMASK, bu);
        unsigned key = (bu == m_w) ? (unsigned)bi : 0xffffffffu;
        unsigned k_w = __reduce_min_sync(FULLMASK, key);
        if (l == 0) { s_wm[w] = m_w; s_wk[w] = k_w; }
        __syncthreads();
        if (t == 0) {
            unsigned bm = s_wm[0], bk = s_wk[0];
#pragma unroll
            for (int w2 = 1; w2 < 4; w2++) {
                if (s_wm[w2] < bm || (s_wm[w2] == bm && s_wk[w2] < bk)) { bm = s_wm[w2]; bk = s_wk[w2]; }
            }
            g_seg_minv[b * 32 + chunk] = funmap(bm);
            g_seg_mini[b * 32 + chunk] = (int)bk;
        }
    }
}

// ---------------- kernel 3: warp-per-(b,r) sorted-list merge -> top-16 ----------------
__global__ void k_topk_merge()
{
    int b = blockIdx.x;        // 32
    int t = threadIdx.x;       // 128
    int w = t >> 5, l = t & 31;

    __shared__ unsigned s_cv[RR][512];   // 8 KB
    __shared__ unsigned s_ci[RR][512];   // 8 KB

    for (int idx = t; idx < RR * 512; idx += 128) {
        s_cv[idx >> 9][idx & 511] = g_cand_v[(size_t)b * RR * 512 + idx];
        s_ci[idx >> 9][idx & 511] = (unsigned)g_cand_i[(size_t)b * RR * 512 + idx];
    }
    __syncthreads();

    // warp w merges 32 sorted 16-lists for r = w; lane l owns chunk l's list
    int br = b * RR + w;
    int p = 0;
    unsigned hv = s_cv[w][l * 16];
    unsigned hk = s_ci[w][l * 16];
    for (int round = 0; round < KK; round++) {
        unsigned m = __reduce_max_sync(FULLMASK, hv);
        unsigned key = (hv == m) ? hk : 0xffffffffu;
        unsigned k = __reduce_min_sync(FULLMASK, key);
        if (l == 0) g_topk[br * KK + round] = (int)k;
        if (hv == m && hk == k) {
            p++;
            if (p < KK) { hv = s_cv[w][l * 16 + p]; hk = s_ci[w][l * 16 + p]; }
            else        { hv = 0u; hk = 0xffffffffu; }
        }
    }
}

// ---------------- kernel 4: argmin combine + gather + cosine softmax ----------------
__global__ void k_final(const float* __restrict__ memory,
                        const int* __restrict__ rpos,
                        float* __restrict__ out)
{
    int b = blockIdx.x;
    int t = threadIdx.x;   // 128

    __shared__ int   s_pos[CC];
    __shared__ int   s_rp[CC];
    __shared__ float s_vm[CC * 33];
    __shared__ float s_norm[CC];
    __shared__ float s_q[RR * WD];
    __shared__ float s_kn[RR];
    __shared__ float s_wt[RR * CC];
    __shared__ float s_v[128];
    __shared__ int   s_i[128];

    s_q[t] = g_rq[b * RR * WD + t];
    if (t < RR * KK) s_pos[t] = g_topk[b * RR * KK + t];
    if (t < CC)      s_rp[t] = rpos[b * CC + t];
    __syncthreads();

    // combine argmin: 32 chunk minima + 65 overridden usage values
    {
        float v = POS_INF;
        int   i = 0x7fffffff;
        if (t < 32) { v = g_seg_minv[b * 32 + t]; i = g_seg_mini[b * 32 + t]; }
        else if (t < 32 + CC) {
            int c = t - 32;
            int p = s_rp[c];
            bool last = true;
            for (int c2 = c + 1; c2 < CC; c2++) if (s_rp[c2] == p) { last = false; break; }
            if (last) { v = g_newusage[b * CC + c]; i = p; }
        }
        s_v[t] = v; s_i[t] = i;
        __syncthreads();
        for (int s = 64; s > 0; s >>= 1) {
            if (t < s) {
                if (s_v[t + s] < s_v[t] || (s_v[t + s] == s_v[t] && s_i[t + s] < s_i[t])) {
                    s_v[t] = s_v[t + s]; s_i[t] = s_i[t + s];
                }
            }
            __syncthreads();
        }
        if (t == 0) s_pos[CC - 1] = s_i[0];
    }
    __syncthreads();

    if (t < RR) {
        float s = 0.f;
        for (int w = 0; w < WD; w++) { float q = s_q[t * WD + w]; s += q * q; }
        s_kn[t] = sqrtf(s) + 1e-6f;
    }
    if (t < CC) {
        int m = s_pos[t];
        m = min(max(m, 0), MM - 1);
        const float* row = memory + ((size_t)b * MM + m) * WD;
        for (int c2 = CC - 1; c2 >= 0; c2--)
            if (s_rp[c2] == m) { row = g_newvis + ((size_t)b * CC + c2) * WD; break; }
        const float4* r4 = (const float4*)row;
        float s = 0.f;
#pragma unroll
        for (int j = 0; j < 8; j++) {
            float4 x = r4[j];
            s_vm[t * 33 + j * 4 + 0] = x.x;
            s_vm[t * 33 + j * 4 + 1] = x.y;
            s_vm[t * 33 + j * 4 + 2] = x.z;
            s_vm[t * 33 + j * 4 + 3] = x.w;
            s += x.x * x.x + x.y * x.y + x.z * x.z + x.w * x.w;
        }
        s_norm[t] = sqrtf(s) + 1e-6f;
    }
    __syncthreads();

    for (int idx = t; idx < RR * CC; idx += 128) {
        int r = idx / CC, c = idx % CC;
        float num = 0.f;
        for (int w = 0; w < WD; w++) num += s_vm[c * 33 + w] * s_q[r * WD + w];
        s_wt[idx] = num / ((float)WD * s_norm[c] * s_kn[r] + 1e-6f);
    }
    __syncthreads();

    if (t < RR) {
        float mx = NEG_INF;
        for (int c = 0; c < CC; c++) mx = fmaxf(mx, s_wt[t * CC + c]);
        float sum = 0.f;
        for (int c = 0; c < CC; c++) { float e = expf(s_wt[t * CC + c] - mx); s_wt[t * CC + c] = e; sum += e; }
        float inv = 1.0f / sum;
        for (int c = 0; c < CC; c++) s_wt[t * CC + c] *= inv;
    }
    __syncthreads();

    {
        int r = t >> 5, w = t & 31;
        float acc = 0.f;
        for (int c = 0; c < CC; c++) acc += s_wt[r * CC + c] * s_vm[c * 33 + w];
        out[b * RR * WD + t] = acc;
    }
}

// ---------------- launch ----------------
extern "C" void kernel_launch(void* const* d_in, const int* in_sizes, int n_in,
                              void* d_out, int out_size)
{
    const float* xi     = (const float*)d_in[0];
    const float* memory = (const float*)d_in[1];
    const float* rw     = (const float*)d_in[2];
    const float* ww     = (const float*)d_in[3];
    const float* usage  = (const float*)d_in[4];
    const float* vis    = (const float*)d_in[5];
    const float* Wrq    = (const float*)d_in[6];
    const float* brq    = (const float*)d_in[7];
    const float* Wwv    = (const float*)d_in[8];
    const float* bwv    = (const float*)d_in[9];
    const float* Wig    = (const float*)d_in[10];
    const float* big    = (const float*)d_in[11];
    const float* Wwg    = (const float*)d_in[12];
    const float* bwg    = (const float*)d_in[13];
    const int*   rpos   = (const int*)d_in[14];
    const int*   tptr   = (n_in > 16) ? (const int*)d_in[16] : nullptr;

    cudaFuncSetAttribute(k_scores, cudaFuncAttributeMaxDynamicSharedMemorySize, 49152);

    k_proj<<<dim3(BB, 4), 128>>>(xi, Wrq, brq, Wwv, bwv, Wig, big, Wwg, bwg);
    k_write<<<BB, 128>>>(rw, ww, usage, vis, rpos, tptr);
    k_scores<<<dim3(32, BB), 128, 49152>>>(memory, usage, rpos);
    k_topk_merge<<<BB, 128>>>();
    k_final<<<BB, 128>>>(memory, rpos, (float*)d_out);
}

// round 12
// speedup vs baseline: 1.1323x; 1.1323x over previous
#include <cuda_runtime.h>
#include <math.h>
#include <stdint.h>

#define BB  32
#define MM  65536
#define WD  32
#define RR  4
#define KK  16
#define CC  65
#define INS 256
#define NEG_INF (-3.402823e38f)
#define POS_INF ( 3.402823e38f)
#define FULLMASK 0xffffffffu

// ---------------- scratch ----------------
__device__ __align__(16) float g_rq[BB * RR * WD];
__device__ __align__(16) float g_proj[BB * 98];          // pre-sigmoid rows 128..225
__device__ __align__(16) float g_newvis[BB * CC * WD];
__device__ float g_newusage[BB * CC];
__device__ int   g_topk[BB * RR * KK];
// candidates: per (b,r): 32 chunks * 16 = 512
__device__ __align__(16) unsigned g_cand_v[BB * RR * 512];
__device__ __align__(16) int      g_cand_i[BB * RR * 512];
// segmented argmin partials: per b: 32 chunks
__device__ float g_seg_minv[BB * 32];
__device__ int   g_seg_mini[BB * 32];

// order-preserving float <-> u32 maps
__device__ __forceinline__ unsigned fmap(float x) {
    unsigned u = __float_as_uint(x);
    return (u & 0x80000000u) ? ~u : (u | 0x80000000u);
}
__device__ __forceinline__ float funmap(unsigned u) {
    unsigned v = (u & 0x80000000u) ? (u & 0x7fffffffu) : ~u;
    return __uint_as_float(v);
}

__device__ __forceinline__ void cp_async16(void* smem_dst, const void* gsrc) {
    unsigned sa = (unsigned)__cvta_generic_to_shared(smem_dst);
    asm volatile("cp.async.cg.shared.global [%0], [%1], 16;\n" :: "r"(sa), "l"(gsrc));
}
#define CP_COMMIT() asm volatile("cp.async.commit_group;\n" ::: "memory")
#define CP_WAIT1()  asm volatile("cp.async.wait_group 1;\n" ::: "memory")

// ---------------- kernel 1a: projections (grid 32 x 4) ----------------
__global__ void k_proj(const float* __restrict__ xi,
                       const float* __restrict__ Wrq, const float* __restrict__ brq,
                       const float* __restrict__ Wwv, const float* __restrict__ bwv,
                       const float* __restrict__ Wig, const float* __restrict__ big,
                       const float* __restrict__ Wwg, const float* __restrict__ bwg)
{
    int b  = blockIdx.x;
    int gy = blockIdx.y;          // 4 groups of 64 rows
    int t = threadIdx.x;          // 128
    int w = t >> 5, l = t & 31;
    int sub = l & 7;

    __shared__ float4 s_xi4[INS / 4];
    if (t < 64) s_xi4[t] = ((const float4*)(xi + b * INS))[t];
    __syncthreads();

#pragma unroll 1
    for (int pass = 0; pass < 4; pass++) {
        int row = gy * 64 + pass * 16 + w * 4 + (l >> 3);
        float acc = 0.f;
        if (row < 226) {
            const float4* wp;
            if (row < 128)      wp = (const float4*)(Wrq + row * INS);
            else if (row < 160) wp = (const float4*)(Wwv + (row - 128) * INS);
            else if (row < 225) wp = (const float4*)(Wig + (row - 160) * INS);
            else                wp = (const float4*)Wwg;
#pragma unroll
            for (int m = 0; m < 8; m++) {
                float4 a = wp[sub + m * 8];
                float4 q = s_xi4[sub + m * 8];
                acc += a.x * q.x + a.y * q.y + a.z * q.z + a.w * q.w;
            }
        }
        acc += __shfl_xor_sync(FULLMASK, acc, 1);
        acc += __shfl_xor_sync(FULLMASK, acc, 2);
        acc += __shfl_xor_sync(FULLMASK, acc, 4);
        if (sub == 0 && row < 226) {
            if (row < 128)      g_rq[b * 128 + row] = acc + brq[row];
            else if (row < 160) g_proj[b * 98 + (row - 128)] = acc + bwv[row - 128];
            else if (row < 225) g_proj[b * 98 + 32 + (row - 160)] = acc + big[row - 160];
            else                g_proj[b * 98 + 97] = acc + bwg[0];
        }
    }
}

// ---------------- kernel 1b: write-phase ----------------
__global__ void k_write(const float* __restrict__ rw,
                        const float* __restrict__ ww,
                        const float* __restrict__ usage,
                        const float* __restrict__ vis,
                        const int* __restrict__ rpos,
                        const int* __restrict__ tptr)
{
    int b = blockIdx.x;
    int t = threadIdx.x;   // 128

    __shared__ float s_wv[WD];
    __shared__ float s_ig[CC];
    __shared__ float s_wg;
    __shared__ float s_ru[CC], s_rwg[CC], s_wwg[CC], s_I[CC], s_wwn[CC];
    __shared__ float s_minu;
    __shared__ int   s_p[CC];

    if (t < 32) s_wv[t] = g_proj[b * 98 + t];
    if (t < CC) s_ig[t] = 1.0f / (1.0f + expf(-g_proj[b * 98 + 32 + t]));
    if (t == 127) s_wg = 1.0f / (1.0f + expf(-g_proj[b * 98 + 97]));

    int ts = tptr ? *tptr : 2;

    if (t < CC) {
        int p = rpos[b * CC + t];
        s_p[t] = p;
        float rg = rw[(size_t)b * MM + p];
        if (ts == 1) rg += 1.0f;
        s_rwg[t] = rg;
        s_wwg[t] = ww[(size_t)b * MM + p];
        s_ru[t]  = usage[(size_t)b * MM + p];
    }
    __syncthreads();
    if (t == 0) {
        float mn = s_ru[0];
        for (int c = 1; c < CC; c++) mn = fminf(mn, s_ru[c]);
        s_minu = mn;
    }
    __syncthreads();
    if (t < CC) {
        float I = (s_ru[t] == s_minu) ? 1.0f : 0.0f;
        s_I[t] = I;
        float u = ((s_rwg[t] + s_wwg[t]) > 0.005f) ? 1.0f : 0.0f;
        float nru = (u > 0.0f) ? ((float)ts - s_ru[t]) : s_ru[t];
        g_newusage[b * CC + t] = nru;
        s_wwn[t] = s_wg * (s_ig[t] * s_rwg[t] + (1.0f - s_ig[t]) * I);
    }
    __syncthreads();
    for (int idx = t; idx < CC * WD; idx += blockDim.x) {
        int c = idx >> 5, ww2 = idx & 31;
        float nv = vis[(size_t)b * CC * WD + idx] * (1.0f - s_I[c]) + s_wwn[c] * s_wv[ww2];
        g_newvis[(size_t)b * CC * WD + idx] = nv;
    }
}

// ---------------- kernel 2: cp.async scores + transposed warp-parallel top-16 + fused argmin ----------------
__global__ void __launch_bounds__(128, 4) k_scores(const float* __restrict__ memory,
                                                   const float* __restrict__ usage,
                                                   const int* __restrict__ rpos)
{
    int b = blockIdx.y;
    int chunk = blockIdx.x;      // 32 chunks of 2048 rows
    int t = threadIdx.x;         // 128
    int w = t >> 5, l = t & 31;
    int chunkbase = chunk * 2048;

    __shared__ float4 s_t[2][128 * 8];   // two 16 KB tiles; reused as 4x2048 score matrix
    __shared__ float4 s_q4[RR * 8];
    __shared__ int   s_p[CC];
    __shared__ int   s_last[CC];
    __shared__ unsigned s_bm[64];        // 2048-bit bitmap of scattered rows in this chunk
    __shared__ unsigned s_wm[4], s_wk[4];

    if (t < 64)     s_bm[t] = 0u;
    if (t < RR * 8) s_q4[t] = ((const float4*)g_rq)[b * RR * 8 + t];
    if (t < CC)     s_p[t] = rpos[b * CC + t];
    __syncthreads();
    if (t < CC) {
        int lastf = 1;
        for (int c2 = t + 1; c2 < CC; c2++) if (s_p[c2] == s_p[t]) { lastf = 0; break; }
        s_last[t] = lastf;
        int p = s_p[t];
        if (p >= chunkbase && p < chunkbase + 2048) {
            int loc = p - chunkbase;
            atomicOr(&s_bm[loc >> 5], 1u << (loc & 31));
        }
    }

    unsigned u0[16], u1[16], u2[16], u3[16];

    const float* gbase = memory + ((size_t)b * MM + chunkbase) * WD;

    // prologue: tile 0
    {
        const float4* src = (const float4*)gbase;
#pragma unroll
        for (int j = 0; j < 8; j++) {
            int f = j * 128 + t;
            int row = f >> 3, col = f & 7;
            cp_async16(&s_t[0][row * 8 + (col ^ (row & 7))], src + f);
        }
        CP_COMMIT();
    }

#pragma unroll
    for (int tile = 0; tile < 16; tile++) {
        int buf = tile & 1;
        __syncthreads();   // everyone done reading buf (2 iters ago); publishes s_bm/s_last on iter 0
        if (tile < 15) {
            const float4* src = (const float4*)(gbase + (size_t)(tile + 1) * 128 * WD);
#pragma unroll
            for (int j = 0; j < 8; j++) {
                int f = j * 128 + t;
                int row = f >> 3, col = f & 7;
                cp_async16(&s_t[buf ^ 1][row * 8 + (col ^ (row & 7))], src + f);
            }
        }
        CP_COMMIT();
        CP_WAIT1();        // current tile's group complete (this thread)
        __syncthreads();   // ... and visible block-wide
        int base = chunkbase + tile * 128;
        if (t < CC && s_last[t]) {
            int p = s_p[t];
            if (p >= base && p < base + 128) {
                int loc = p - base;
                const float4* nv = (const float4*)(g_newvis + ((size_t)b * CC + t) * WD);
#pragma unroll
                for (int j = 0; j < 8; j++) s_t[buf][loc * 8 + (j ^ (loc & 7))] = nv[j];
            }
        }
        __syncthreads();
        float a0 = 0.f, a1 = 0.f, a2 = 0.f, a3 = 0.f;
#pragma unroll
        for (int j = 0; j < 8; j++) {
            float4 x = s_t[buf][t * 8 + (j ^ (t & 7))];
            float4 q0 = s_q4[j], q1 = s_q4[8 + j], q2 = s_q4[16 + j], q3 = s_q4[24 + j];
            a0 += x.x * q0.x + x.y * q0.y + x.z * q0.z + x.w * q0.w;
            a1 += x.x * q1.x + x.y * q1.y + x.z * q1.z + x.w * q1.w;
            a2 += x.x * q2.x + x.y * q2.y + x.z * q2.z + x.w * q2.w;
            a3 += x.x * q3.x + x.y * q3.y + x.z * q3.z + x.w * q3.w;
        }
        u0[tile] = fmap(a0); u1[tile] = fmap(a1);
        u2[tile] = fmap(a2); u3[tile] = fmap(a3);
    }

    // ---- transpose scores into smem (tile buffers are free now) ----
    __syncthreads();   // all tile reads done before overwrite
    unsigned* s_sc = (unsigned*)&s_t[0][0];   // 4 * 2048 u32 = 32 KB
#pragma unroll
    for (int tile = 0; tile < 16; tile++) {
        int rowi = tile * 128 + t;
        s_sc[0 * 2048 + rowi] = u0[tile];
        s_sc[1 * 2048 + rowi] = u1[tile];
        s_sc[2 * 2048 + rowi] = u2[tile];
        s_sc[3 * 2048 + rowi] = u3[tile];
    }
    __syncthreads();

    // ---- warp w selects top-16 of 2048 scores for query r = w ----
    // lane l owns rows {j*32 + l}, j = 0..63 (conflict-free LDS)
    {
        const unsigned* sc = s_sc + w * 2048;
        unsigned m1 = 0u, m2 = 0u;
        int i1 = l, i2 = l;
        for (int j = 0; j < 64; j++) {
            unsigned v = sc[j * 32 + l];
            int idx = j * 32 + l;
            if (v > m1)      { m2 = m1; i2 = i1; m1 = v; i1 = idx; }
            else if (v > m2) { m2 = v; i2 = idx; }
        }
        unsigned rem_lo = 0u, rem_hi = 0u;   // consumed-slot mask (by j)
        bool have2 = true;
        unsigned lm = m1; int li = i1;

        unsigned* outv = g_cand_v + ((size_t)(b * RR) * 32 + chunk) * 16 + (size_t)w * 32 * 16;
        int*      outi = g_cand_i + ((size_t)(b * RR) * 32 + chunk) * 16 + (size_t)w * 32 * 16;

        for (int round = 0; round < 16; round++) {
            unsigned m = __reduce_max_sync(FULLMASK, lm);
            unsigned key = (lm == m) ? (unsigned)li : 0xffffffffu;
            unsigned k = __reduce_min_sync(FULLMASK, key);
            if (l == 0) { outv[round] = m; outi[round] = chunkbase + (int)k; }
            if (lm == m && (unsigned)li == k) {
                int j = li >> 5;             // owned slot index
                if (j < 32) rem_lo |= 1u << j; else rem_hi |= 1u << (j - 32);
                if (have2) { lm = m2; li = i2; have2 = false; }
                else {
                    lm = 0u; li = l;
                    for (int jj = 0; jj < 64; jj++) {
                        bool rm = (jj < 32) ? ((rem_lo >> jj) & 1u) : ((rem_hi >> (jj - 32)) & 1u);
                        unsigned v = rm ? 0u : sc[jj * 32 + l];
                        if (v > lm) { lm = v; li = jj * 32 + l; }
                    }
                }
            }
        }
    }

    // ---- fused usage argmin over this chunk (excluding scattered rows) ----
    {
        const float4* u4 = (const float4*)(usage + (size_t)b * MM + chunkbase);
        unsigned bu = 0xffffffffu;
        int      bi = 0x7fffffff;
#pragma unroll
        for (int i = 0; i < 4; i++) {
            float4 x = u4[i * 128 + t];
            int lbase = (i * 128 + t) << 2;
            float xs[4] = {x.x, x.y, x.z, x.w};
#pragma unroll
            for (int j = 0; j < 4; j++) {
                int loc = lbase + j;
                unsigned uv = ((s_bm[loc >> 5] >> (loc & 31)) & 1u) ? 0xffffffffu : fmap(xs[j]);
                int gi = chunkbase + loc;
                if (uv < bu || (uv == bu && gi < bi)) { bu = uv; bi = gi; }
            }
        }
        unsigned m_w = __reduce_min_sync(FULLMASK, bu);
        unsigned key = (bu == m_w) ? (unsigned)bi : 0xffffffffu;
        unsigned k_w = __reduce_min_sync(FULLMASK, key);
        if (l == 0) { s_wm[w] = m_w; s_wk[w] = k_w; }
        __syncthreads();
        if (t == 0) {
            unsigned bm = s_wm[0], bk = s_wk[0];
#pragma unroll
            for (int w2 = 1; w2 < 4; w2++) {
                if (s_wm[w2] < bm || (s_wm[w2] == bm && s_wk[w2] < bk)) { bm = s_wm[w2]; bk = s_wk[w2]; }
            }
            g_seg_minv[b * 32 + chunk] = funmap(bm);
            g_seg_mini[b * 32 + chunk] = (int)bk;
        }
    }
}

// ---------------- kernel 3: merge 512 candidates -> top-16 per (b,r) ----------------
__global__ void k_topk_merge()
{
    int br = blockIdx.x;    // 128
    int t = threadIdx.x;    // 256
    int w = t >> 5, l = t & 31;

    __shared__ unsigned s_wm[16], s_wk[16];
    __shared__ unsigned s_bm2[2], s_bk2[2];

    const unsigned* cv = g_cand_v + (size_t)br * 512;
    const int*      ci = g_cand_i + (size_t)br * 512;
    unsigned v0 = cv[t],       v1 = cv[256 + t];
    unsigned i0 = (unsigned)ci[t], i1 = (unsigned)ci[256 + t];

    for (int round = 0; round < 16; round++) {
        int par = round & 1;
        unsigned lv, li;
        if (v0 > v1 || (v0 == v1 && i0 < i1)) { lv = v0; li = i0; }
        else                                  { lv = v1; li = i1; }
        unsigned m_w = __reduce_max_sync(FULLMASK, lv);
        unsigned key = (lv == m_w) ? li : 0xffffffffu;
        unsigned k_w = __reduce_min_sync(FULLMASK, key);
        if (l == 0) { s_wm[par * 8 + w] = m_w; s_wk[par * 8 + w] = k_w; }
        __syncthreads();
        if (t == 0) {
            unsigned bm = s_wm[par * 8], bk = s_wk[par * 8];
#pragma unroll
            for (int w2 = 1; w2 < 8; w2++) {
                unsigned vm2 = s_wm[par * 8 + w2], vk2 = s_wk[par * 8 + w2];
                if (vm2 > bm || (vm2 == bm && vk2 < bk)) { bm = vm2; bk = vk2; }
            }
            s_bm2[par] = bm; s_bk2[par] = bk;
            g_topk[br * KK + round] = (int)bk;
        }
        __syncthreads();
        unsigned bk = s_bk2[par];
        if (i0 == bk) v0 = 0u;
        if (i1 == bk) v1 = 0u;
    }
}

// ---------------- kernel 4: argmin combine + gather + cosine softmax ----------------
__global__ void k_final(const float* __restrict__ memory,
                        const int* __restrict__ rpos,
                        float* __restrict__ out)
{
    int b = blockIdx.x;
    int t = threadIdx.x;   // 128

    __shared__ int   s_pos[CC];
    __shared__ int   s_rp[CC];
    __shared__ float s_vm[CC * 33];
    __shared__ float s_norm[CC];
    __shared__ float s_q[RR * WD];
    __shared__ float s_kn[RR];
    __shared__ float s_wt[RR * CC];
    __shared__ float s_v[128];
    __shared__ int   s_i[128];

    s_q[t] = g_rq[b * RR * WD + t];
    if (t < RR * KK) s_pos[t] = g_topk[b * RR * KK + t];
    if (t < CC)      s_rp[t] = rpos[b * CC + t];
    __syncthreads();

    // combine argmin: 32 chunk minima + 65 overridden usage values
    {
        float v = POS_INF;
        int   i = 0x7fffffff;
        if (t < 32) { v = g_seg_minv[b * 32 + t]; i = g_seg_mini[b * 32 + t]; }
        else if (t < 32 + CC) {
            int c = t - 32;
            int p = s_rp[c];
            bool last = true;
            for (int c2 = c + 1; c2 < CC; c2++) if (s_rp[c2] == p) { last = false; break; }
            if (last) { v = g_newusage[b * CC + c]; i = p; }
        }
        s_v[t] = v; s_i[t] = i;
        __syncthreads();
        for (int s = 64; s > 0; s >>= 1) {
            if (t < s) {
                if (s_v[t + s] < s_v[t] || (s_v[t + s] == s_v[t] && s_i[t + s] < s_i[t])) {
                    s_v[t] = s_v[t + s]; s_i[t] = s_i[t + s];
                }
            }
            __syncthreads();
        }
        if (t == 0) s_pos[CC - 1] = s_i[0];
    }
    __syncthreads();

    if (t < RR) {
        float s = 0.f;
        for (int w = 0; w < WD; w++) { float q = s_q[t * WD + w]; s += q * q; }
        s_kn[t] = sqrtf(s) + 1e-6f;
    }
    if (t < CC) {
        int m = s_pos[t];
        m = min(max(m, 0), MM - 1);
        const float* row = memory + ((size_t)b * MM + m) * WD;
        for (int c2 = CC - 1; c2 >= 0; c2--)
            if (s_rp[c2] == m) { row = g_newvis + ((size_t)b * CC + c2) * WD; break; }
        const float4* r4 = (const float4*)row;
        float s = 0.f;
#pragma unroll
        for (int j = 0; j < 8; j++) {
            float4 x = r4[j];
            s_vm[t * 33 + j * 4 + 0] = x.x;
            s_vm[t * 33 + j * 4 + 1] = x.y;
            s_vm[t * 33 + j * 4 + 2] = x.z;
            s_vm[t * 33 + j * 4 + 3] = x.w;
            s += x.x * x.x + x.y * x.y + x.z * x.z + x.w * x.w;
        }
        s_norm[t] = sqrtf(s) + 1e-6f;
    }
    __syncthreads();

    for (int idx = t; idx < RR * CC; idx += 128) {
        int r = idx / CC, c = idx % CC;
        float num = 0.f;
        for (int w = 0; w < WD; w++) num += s_vm[c * 33 + w] * s_q[r * WD + w];
        s_wt[idx] = num / ((float)WD * s_norm[c] * s_kn[r] + 1e-6f);
    }
    __syncthreads();

    if (t < RR) {
        float mx = NEG_INF;
        for (int c = 0; c < CC; c++) mx = fmaxf(mx, s_wt[t * CC + c]);
        float sum = 0.f;
        for (int c = 0; c < CC; c++) { float e = expf(s_wt[t * CC + c] - mx); s_wt[t * CC + c] = e; sum += e; }
        float inv = 1.0f / sum;
        for (int c = 0; c < CC; c++) s_wt[t * CC + c] *= inv;
    }
    __syncthreads();

    {
        int r = t >> 5, w = t & 31;
        float acc = 0.f;
        for (int c = 0; c < CC; c++) acc += s_wt[r * CC + c] * s_vm[c * 33 + w];
        out[b * RR * WD + t] = acc;
    }
}

// ---------------- launch ----------------
extern "C" void kernel_launch(void* const* d_in, const int* in_sizes, int n_in,
                              void* d_out, int out_size)
{
    const float* xi     = (const float*)d_in[0];
    const float* memory = (const float*)d_in[1];
    const float* rw     = (const float*)d_in[2];
    const float* ww     = (const float*)d_in[3];
    const float* usage  = (const float*)d_in[4];
    const float* vis    = (const float*)d_in[5];
    const float* Wrq    = (const float*)d_in[6];
    const float* brq    = (const float*)d_in[7];
    const float* Wwv    = (const float*)d_in[8];
    const float* bwv    = (const float*)d_in[9];
    const float* Wig    = (const float*)d_in[10];
    const float* big    = (const float*)d_in[11];
    const float* Wwg    = (const float*)d_in[12];
    const float* bwg    = (const float*)d_in[13];
    const int*   rpos   = (const int*)d_in[14];
    const int*   tptr   = (n_in > 16) ? (const int*)d_in[16] : nullptr;

    k_proj<<<dim3(BB, 4), 128>>>(xi, Wrq, brq, Wwv, bwv, Wig, big, Wwg, bwg);
    k_write<<<BB, 128>>>(rw, ww, usage, vis, rpos, tptr);
    k_scores<<<dim3(32, BB), 128>>>(memory, usage, rpos);
    k_topk_merge<<<BB * RR, 256>>>();
    k_final<<<BB, 128>>>(memory, rpos, (float*)d_out);
}

// round 13
// speedup vs baseline: 1.1787x; 1.0409x over previous
#include <cuda_runtime.h>
#include <math.h>
#include <stdint.h>

#define BB  32
#define MM  65536
#define WD  32
#define RR  4
#define KK  16
#define CC  65
#define INS 256
#define NEG_INF (-3.402823e38f)
#define POS_INF ( 3.402823e38f)
#define FULLMASK 0xffffffffu

// ---------------- scratch ----------------
__device__ __align__(16) float g_rq[BB * RR * WD];
__device__ __align__(16) float g_proj[BB * 98];          // pre-sigmoid rows 128..225
__device__ __align__(16) float g_newvis[BB * CC * WD];
__device__ float g_newusage[BB * CC];
__device__ int   g_topk[BB * RR * KK];
// candidates: per (b,r): 32 chunks * 16 = 512 (each chunk-list sorted desc, ties index-asc)
__device__ __align__(16) unsigned g_cand_v[BB * RR * 512];
__device__ __align__(16) int      g_cand_i[BB * RR * 512];
// segmented argmin partials: per b: 32 chunks
__device__ float g_seg_minv[BB * 32];
__device__ int   g_seg_mini[BB * 32];

// order-preserving float <-> u32 maps
__device__ __forceinline__ unsigned fmap(float x) {
    unsigned u = __float_as_uint(x);
    return (u & 0x80000000u) ? ~u : (u | 0x80000000u);
}
__device__ __forceinline__ float funmap(unsigned u) {
    unsigned v = (u & 0x80000000u) ? (u & 0x7fffffffu) : ~u;
    return __uint_as_float(v);
}

__device__ __forceinline__ void cp_async16(void* smem_dst, const void* gsrc) {
    unsigned sa = (unsigned)__cvta_generic_to_shared(smem_dst);
    asm volatile("cp.async.cg.shared.global [%0], [%1], 16;\n" :: "r"(sa), "l"(gsrc));
}
#define CP_COMMIT() asm volatile("cp.async.commit_group;\n" ::: "memory")
#define CP_WAIT1()  asm volatile("cp.async.wait_group 1;\n" ::: "memory")

// ---------------- kernel 1a: projections (grid 32 x 4) ----------------
__global__ void k_proj(const float* __restrict__ xi,
                       const float* __restrict__ Wrq, const float* __restrict__ brq,
                       const float* __restrict__ Wwv, const float* __restrict__ bwv,
                       const float* __restrict__ Wig, const float* __restrict__ big,
                       const float* __restrict__ Wwg, const float* __restrict__ bwg)
{
    int b  = blockIdx.x;
    int gy = blockIdx.y;          // 4 groups of 64 rows
    int t = threadIdx.x;          // 128
    int w = t >> 5, l = t & 31;
    int sub = l & 7;

    __shared__ float4 s_xi4[INS / 4];
    if (t < 64) s_xi4[t] = ((const float4*)(xi + b * INS))[t];
    __syncthreads();

#pragma unroll 1
    for (int pass = 0; pass < 4; pass++) {
        int row = gy * 64 + pass * 16 + w * 4 + (l >> 3);
        float acc = 0.f;
        if (row < 226) {
            const float4* wp;
            if (row < 128)      wp = (const float4*)(Wrq + row * INS);
            else if (row < 160) wp = (const float4*)(Wwv + (row - 128) * INS);
            else if (row < 225) wp = (const float4*)(Wig + (row - 160) * INS);
            else                wp = (const float4*)Wwg;
#pragma unroll
            for (int m = 0; m < 8; m++) {
                float4 a = wp[sub + m * 8];
                float4 q = s_xi4[sub + m * 8];
                acc += a.x * q.x + a.y * q.y + a.z * q.z + a.w * q.w;
            }
        }
        acc += __shfl_xor_sync(FULLMASK, acc, 1);
        acc += __shfl_xor_sync(FULLMASK, acc, 2);
        acc += __shfl_xor_sync(FULLMASK, acc, 4);
        if (sub == 0 && row < 226) {
            if (row < 128)      g_rq[b * 128 + row] = acc + brq[row];
            else if (row < 160) g_proj[b * 98 + (row - 128)] = acc + bwv[row - 128];
            else if (row < 225) g_proj[b * 98 + 32 + (row - 160)] = acc + big[row - 160];
            else                g_proj[b * 98 + 97] = acc + bwg[0];
        }
    }
}

// ---------------- kernel 1b: write-phase ----------------
__global__ void k_write(const float* __restrict__ rw,
                        const float* __restrict__ ww,
                        const float* __restrict__ usage,
                        const float* __restrict__ vis,
                        const int* __restrict__ rpos,
                        const int* __restrict__ tptr)
{
    int b = blockIdx.x;
    int t = threadIdx.x;   // 128

    __shared__ float s_wv[WD];
    __shared__ float s_ig[CC];
    __shared__ float s_wg;
    __shared__ float s_ru[CC], s_rwg[CC], s_wwg[CC], s_I[CC], s_wwn[CC];
    __shared__ float s_minu;
    __shared__ int   s_p[CC];

    if (t < 32) s_wv[t] = g_proj[b * 98 + t];
    if (t < CC) s_ig[t] = 1.0f / (1.0f + expf(-g_proj[b * 98 + 32 + t]));
    if (t == 127) s_wg = 1.0f / (1.0f + expf(-g_proj[b * 98 + 97]));

    int ts = tptr ? *tptr : 2;

    if (t < CC) {
        int p = rpos[b * CC + t];
        s_p[t] = p;
        float rg = rw[(size_t)b * MM + p];
        if (ts == 1) rg += 1.0f;
        s_rwg[t] = rg;
        s_wwg[t] = ww[(size_t)b * MM + p];
        s_ru[t]  = usage[(size_t)b * MM + p];
    }
    __syncthreads();
    if (t == 0) {
        float mn = s_ru[0];
        for (int c = 1; c < CC; c++) mn = fminf(mn, s_ru[c]);
        s_minu = mn;
    }
    __syncthreads();
    if (t < CC) {
        float I = (s_ru[t] == s_minu) ? 1.0f : 0.0f;
        s_I[t] = I;
        float u = ((s_rwg[t] + s_wwg[t]) > 0.005f) ? 1.0f : 0.0f;
        float nru = (u > 0.0f) ? ((float)ts - s_ru[t]) : s_ru[t];
        g_newusage[b * CC + t] = nru;
        s_wwn[t] = s_wg * (s_ig[t] * s_rwg[t] + (1.0f - s_ig[t]) * I);
    }
    __syncthreads();
    for (int idx = t; idx < CC * WD; idx += blockDim.x) {
        int c = idx >> 5, ww2 = idx & 31;
        float nv = vis[(size_t)b * CC * WD + idx] * (1.0f - s_I[c]) + s_wwn[c] * s_wv[ww2];
        g_newvis[(size_t)b * CC * WD + idx] = nv;
    }
}

// ---------------- kernel 2: cp.async scores + transposed warp-parallel top-16 + fused argmin ----------------
__global__ void __launch_bounds__(128, 4) k_scores(const float* __restrict__ memory,
                                                   const float* __restrict__ usage,
                                                   const int* __restrict__ rpos)
{
    int b = blockIdx.y;
    int chunk = blockIdx.x;      // 32 chunks of 2048 rows
    int t = threadIdx.x;         // 128
    int w = t >> 5, l = t & 31;
    int chunkbase = chunk * 2048;

    __shared__ float4 s_t[2][128 * 8];   // two 16 KB tiles; reused as 4x2048 score matrix
    __shared__ float4 s_q4[RR * 8];
    __shared__ int   s_p[CC];
    __shared__ int   s_last[CC];
    __shared__ unsigned s_bm[64];        // 2048-bit bitmap of scattered rows in this chunk
    __shared__ unsigned s_wm[4], s_wk[4];

    if (t < 64)     s_bm[t] = 0u;
    if (t < RR * 8) s_q4[t] = ((const float4*)g_rq)[b * RR * 8 + t];
    if (t < CC)     s_p[t] = rpos[b * CC + t];
    __syncthreads();
    if (t < CC) {
        int lastf = 1;
        for (int c2 = t + 1; c2 < CC; c2++) if (s_p[c2] == s_p[t]) { lastf = 0; break; }
        s_last[t] = lastf;
        int p = s_p[t];
        if (p >= chunkbase && p < chunkbase + 2048) {
            int loc = p - chunkbase;
            atomicOr(&s_bm[loc >> 5], 1u << (loc & 31));
        }
    }

    unsigned u0[16], u1[16], u2[16], u3[16];

    const float* gbase = memory + ((size_t)b * MM + chunkbase) * WD;

    // prologue: tile 0
    {
        const float4* src = (const float4*)gbase;
#pragma unroll
        for (int j = 0; j < 8; j++) {
            int f = j * 128 + t;
            int row = f >> 3, col = f & 7;
            cp_async16(&s_t[0][row * 8 + (col ^ (row & 7))], src + f);
        }
        CP_COMMIT();
    }

#pragma unroll
    for (int tile = 0; tile < 16; tile++) {
        int buf = tile & 1;
        __syncthreads();   // everyone done reading buf (2 iters ago); publishes s_bm/s_last on iter 0
        if (tile < 15) {
            const float4* src = (const float4*)(gbase + (size_t)(tile + 1) * 128 * WD);
#pragma unroll
            for (int j = 0; j < 8; j++) {
                int f = j * 128 + t;
                int row = f >> 3, col = f & 7;
                cp_async16(&s_t[buf ^ 1][row * 8 + (col ^ (row & 7))], src + f);
            }
        }
        CP_COMMIT();
        CP_WAIT1();        // current tile's group complete (this thread)
        __syncthreads();   // ... and visible block-wide
        int base = chunkbase + tile * 128;
        if (t < CC && s_last[t]) {
            int p = s_p[t];
            if (p >= base && p < base + 128) {
                int loc = p - base;
                const float4* nv = (const float4*)(g_newvis + ((size_t)b * CC + t) * WD);
#pragma unroll
                for (int j = 0; j < 8; j++) s_t[buf][loc * 8 + (j ^ (loc & 7))] = nv[j];
            }
        }
        __syncthreads();
        float a0 = 0.f, a1 = 0.f, a2 = 0.f, a3 = 0.f;
#pragma unroll
        for (int j = 0; j < 8; j++) {
            float4 x = s_t[buf][t * 8 + (j ^ (t & 7))];
            float4 q0 = s_q4[j], q1 = s_q4[8 + j], q2 = s_q4[16 + j], q3 = s_q4[24 + j];
            a0 += x.x * q0.x + x.y * q0.y + x.z * q0.z + x.w * q0.w;
            a1 += x.x * q1.x + x.y * q1.y + x.z * q1.z + x.w * q1.w;
            a2 += x.x * q2.x + x.y * q2.y + x.z * q2.z + x.w * q2.w;
            a3 += x.x * q3.x + x.y * q3.y + x.z * q3.z + x.w * q3.w;
        }
        u0[tile] = fmap(a0); u1[tile] = fmap(a1);
        u2[tile] = fmap(a2); u3[tile] = fmap(a3);
    }

    // ---- transpose scores into smem (tile buffers are free now) ----
    __syncthreads();   // all tile reads done before overwrite
    unsigned* s_sc = (unsigned*)&s_t[0][0];   // 4 * 2048 u32 = 32 KB
#pragma unroll
    for (int tile = 0; tile < 16; tile++) {
        int rowi = tile * 128 + t;
        s_sc[0 * 2048 + rowi] = u0[tile];
        s_sc[1 * 2048 + rowi] = u1[tile];
        s_sc[2 * 2048 + rowi] = u2[tile];
        s_sc[3 * 2048 + rowi] = u3[tile];
    }
    __syncthreads();

    // ---- warp w selects top-16 of 2048 scores for query r = w ----
    // lane l owns rows {j*32 + l}, j = 0..63 (conflict-free LDS)
    {
        const unsigned* sc = s_sc + w * 2048;
        unsigned m1 = 0u, m2 = 0u;
        int i1 = l, i2 = l;
        for (int j = 0; j < 64; j++) {
            unsigned v = sc[j * 32 + l];
            int idx = j * 32 + l;
            if (v > m1)      { m2 = m1; i2 = i1; m1 = v; i1 = idx; }
            else if (v > m2) { m2 = v; i2 = idx; }
        }
        unsigned rem_lo = 0u, rem_hi = 0u;   // consumed-slot mask (by j)
        bool have2 = true;
        unsigned lm = m1; int li = i1;

        unsigned* outv = g_cand_v + ((size_t)(b * RR) * 32 + chunk) * 16 + (size_t)w * 32 * 16;
        int*      outi = g_cand_i + ((size_t)(b * RR) * 32 + chunk) * 16 + (size_t)w * 32 * 16;

        for (int round = 0; round < 16; round++) {
            unsigned m = __reduce_max_sync(FULLMASK, lm);
            unsigned key = (lm == m) ? (unsigned)li : 0xffffffffu;
            unsigned k = __reduce_min_sync(FULLMASK, key);
            if (l == 0) { outv[round] = m; outi[round] = chunkbase + (int)k; }
            if (lm == m && (unsigned)li == k) {
                int j = li >> 5;             // owned slot index
                if (j < 32) rem_lo |= 1u << j; else rem_hi |= 1u << (j - 32);
                if (have2) { lm = m2; li = i2; have2 = false; }
                else {
                    lm = 0u; li = l;
                    for (int jj = 0; jj < 64; jj++) {
                        bool rm = (jj < 32) ? ((rem_lo >> jj) & 1u) : ((rem_hi >> (jj - 32)) & 1u);
                        unsigned v = rm ? 0u : sc[jj * 32 + l];
                        if (v > lm) { lm = v; li = jj * 32 + l; }
                    }
                }
            }
        }
    }

    // ---- fused usage argmin over this chunk (excluding scattered rows) ----
    {
        const float4* u4 = (const float4*)(usage + (size_t)b * MM + chunkbase);
        unsigned bu = 0xffffffffu;
        int      bi = 0x7fffffff;
#pragma unroll
        for (int i = 0; i < 4; i++) {
            float4 x = u4[i * 128 + t];
            int lbase = (i * 128 + t) << 2;
            float xs[4] = {x.x, x.y, x.z, x.w};
#pragma unroll
            for (int j = 0; j < 4; j++) {
                int loc = lbase + j;
                unsigned uv = ((s_bm[loc >> 5] >> (loc & 31)) & 1u) ? 0xffffffffu : fmap(xs[j]);
                int gi = chunkbase + loc;
                if (uv < bu || (uv == bu && gi < bi)) { bu = uv; bi = gi; }
            }
        }
        unsigned m_w = __reduce_min_sync(FULLMASK, bu);
        unsigned key = (bu == m_w) ? (unsigned)bi : 0xffffffffu;
        unsigned k_w = __reduce_min_sync(FULLMASK, key);
        if (l == 0) { s_wm[w] = m_w; s_wk[w] = k_w; }
        __syncthreads();
        if (t == 0) {
            unsigned bm = s_wm[0], bk = s_wk[0];
#pragma unroll
            for (int w2 = 1; w2 < 4; w2++) {
                if (s_wm[w2] < bm || (s_wm[w2] == bm && s_wk[w2] < bk)) { bm = s_wm[w2]; bk = s_wk[w2]; }
            }
            g_seg_minv[b * 32 + chunk] = funmap(bm);
            g_seg_mini[b * 32 + chunk] = (int)bk;
        }
    }
}

// ---------------- kernel 3: warp-per-(b,r) sorted-list merge (grid 128 x 32 thr) ----------------
__global__ void k_topk_merge()
{
    int br = blockIdx.x;    // 128
    int l = threadIdx.x;    // 32 (one warp)

    __shared__ unsigned s_cv[512];
    __shared__ unsigned s_ci[512];

    const unsigned* cv = g_cand_v + (size_t)br * 512;
    const int*      ci = g_cand_i + (size_t)br * 512;
#pragma unroll
    for (int k = 0; k < 16; k++) {
        s_cv[k * 32 + l] = cv[k * 32 + l];
        s_ci[k * 32 + l] = (unsigned)ci[k * 32 + l];
    }
    __syncwarp();

    // lane l owns chunk l's sorted 16-list
    int p = 0;
    unsigned hv = s_cv[l * 16];
    unsigned hk = s_ci[l * 16];
    for (int round = 0; round < KK; round++) {
        unsigned m = __reduce_max_sync(FULLMASK, hv);
        unsigned key = (hv == m) ? hk : 0xffffffffu;
        unsigned k = __reduce_min_sync(FULLMASK, key);
        if (l == 0) g_topk[br * KK + round] = (int)k;
        if (hv == m && hk == k) {
            p++;
            if (p < KK) { hv = s_cv[l * 16 + p]; hk = s_ci[l * 16 + p]; }
            else        { hv = 0u; hk = 0xffffffffu; }
        }
    }
}

// ---------------- kernel 4: argmin combine + gather + cosine softmax (256 thr) ----------------
__global__ void k_final(const float* __restrict__ memory,
                        const int* __restrict__ rpos,
                        float* __restrict__ out)
{
    int b = blockIdx.x;
    int t = threadIdx.x;   // 256
    int w = t >> 5, l = t & 31;

    __shared__ int   s_pos[CC];
    __shared__ int   s_rp[CC];
    __shared__ float s_vm[CC * 33];
    __shared__ float s_norm[CC];
    __shared__ float s_q[RR * WD];
    __shared__ float s_kn[RR];
    __shared__ float s_wt[RR * CC];
    __shared__ float s_v[128];
    __shared__ int   s_i[128];

    if (t < RR * WD) s_q[t] = g_rq[b * RR * WD + t];
    if (t < RR * KK) s_pos[t] = g_topk[b * RR * KK + t];
    if (t < CC)      s_rp[t] = rpos[b * CC + t];
    __syncthreads();

    // combine argmin: 32 chunk minima + 65 overridden usage values
    {
        float v = POS_INF;
        int   i = 0x7fffffff;
        if (t < 32) { v = g_seg_minv[b * 32 + t]; i = g_seg_mini[b * 32 + t]; }
        else if (t < 32 + CC) {
            int c = t - 32;
            int p = s_rp[c];
            bool last = true;
            for (int c2 = c + 1; c2 < CC; c2++) if (s_rp[c2] == p) { last = false; break; }
            if (last) { v = g_newusage[b * CC + c]; i = p; }
        }
        if (t < 128) { s_v[t] = v; s_i[t] = i; }
        __syncthreads();
        for (int s = 64; s > 0; s >>= 1) {
            if (t < s) {
                if (s_v[t + s] < s_v[t] || (s_v[t + s] == s_v[t] && s_i[t + s] < s_i[t])) {
                    s_v[t] = s_v[t + s]; s_i[t] = s_i[t + s];
                }
            }
            __syncthreads();
        }
        if (t == 0) s_pos[CC - 1] = s_i[0];
    }
    __syncthreads();

    if (t < RR) {
        float s = 0.f;
        for (int ww2 = 0; ww2 < WD; ww2++) { float q = s_q[t * WD + ww2]; s += q * q; }
        s_kn[t] = sqrtf(s) + 1e-6f;
    }
    if (t < CC) {
        int m = s_pos[t];
        m = min(max(m, 0), MM - 1);
        const float* row = memory + ((size_t)b * MM + m) * WD;
        for (int c2 = CC - 1; c2 >= 0; c2--)
            if (s_rp[c2] == m) { row = g_newvis + ((size_t)b * CC + c2) * WD; break; }
        const float4* r4 = (const float4*)row;
        float s = 0.f;
#pragma unroll
        for (int j = 0; j < 8; j++) {
            float4 x = r4[j];
            s_vm[t * 33 + j * 4 + 0] = x.x;
            s_vm[t * 33 + j * 4 + 1] = x.y;
            s_vm[t * 33 + j * 4 + 2] = x.z;
            s_vm[t * 33 + j * 4 + 3] = x.w;
            s += x.x * x.x + x.y * x.y + x.z * x.z + x.w * x.w;
        }
        s_norm[t] = sqrtf(s) + 1e-6f;
    }
    __syncthreads();

    for (int idx = t; idx < RR * CC; idx += 256) {
        int r = idx / CC, c = idx % CC;
        float num = 0.f;
#pragma unroll 8
        for (int ww2 = 0; ww2 < WD; ww2++) num += s_vm[c * 33 + ww2] * s_q[r * WD + ww2];
        s_wt[idx] = num / ((float)WD * s_norm[c] * s_kn[r] + 1e-6f);
    }
    __syncthreads();

    // warp-parallel softmax: warp w handles r = w over 65 entries
    if (w < RR) {
        float v0 = s_wt[w * CC + l];
        float v1 = s_wt[w * CC + 32 + l];
        float v2 = (l == 0) ? s_wt[w * CC + 64] : NEG_INF;
        float mx = fmaxf(v0, fmaxf(v1, v2));
#pragma unroll
        for (int off = 16; off; off >>= 1) mx = fmaxf(mx, __shfl_xor_sync(FULLMASK, mx, off));
        float e0 = expf(v0 - mx), e1 = expf(v1 - mx);
        float e2 = (l == 0) ? expf(v2 - mx) : 0.f;
        float sum = e0 + e1 + e2;
#pragma unroll
        for (int off = 16; off; off >>= 1) sum += __shfl_xor_sync(FULLMASK, sum, off);
        float inv = 1.0f / sum;
        s_wt[w * CC + l] = e0 * inv;
        s_wt[w * CC + 32 + l] = e1 * inv;
        if (l == 0) s_wt[w * CC + 64] = e2 * inv;
    }
    __syncthreads();

    if (t < 128) {
        int r = t >> 5, ww2 = t & 31;
        float acc = 0.f;
        for (int c = 0; c < CC; c++) acc += s_wt[r * CC + c] * s_vm[c * 33 + ww2];
        out[b * RR * WD + t] = acc;
    }
}

// ---------------- launch ----------------
extern "C" void kernel_launch(void* const* d_in, const int* in_sizes, int n_in,
                              void* d_out, int out_size)
{
    const float* xi     = (const float*)d_in[0];
    const float* memory = (const float*)d_in[1];
    const float* rw     = (const float*)d_in[2];
    const float* ww     = (const float*)d_in[3];
    const float* usage  = (const float*)d_in[4];
    const float* vis    = (const float*)d_in[5];
    const float* Wrq    = (const float*)d_in[6];
    const float* brq    = (const float*)d_in[7];
    const float* Wwv    = (const float*)d_in[8];
    const float* bwv    = (const float*)d_in[9];
    const float* Wig    = (const float*)d_in[10];
    const float* big    = (const float*)d_in[11];
    const float* Wwg    = (const float*)d_in[12];
    const float* bwg    = (const float*)d_in[13];
    const int*   rpos   = (const int*)d_in[14];
    const int*   tptr   = (n_in > 16) ? (const int*)d_in[16] : nullptr;

    k_proj<<<dim3(BB, 4), 128>>>(xi, Wrq, brq, Wwv, bwv, Wig, big, Wwg, bwg);
    k_write<<<BB, 128>>>(rw, ww, usage, vis, rpos, tptr);
    k_scores<<<dim3(32, BB), 128>>>(memory, usage, rpos);
    k_topk_merge<<<BB * RR, 32>>>();
    k_final<<<BB, 256>>>(memory, rpos, (float*)d_out);
}